// round 13
// baseline (speedup 1.0000x reference)
#include <cuda_runtime.h>
#include <cuda_bf16.h>
#include <stdint.h>
#include <math.h>

#define NROWS 8192
#define HALF_N 4096
#define DDIM 256
#define NCTA 148

// Scratch (allocation-free rule: __device__ globals)
__device__ __nv_bfloat16 g_reps[NROWS * DDIM];  // normalized * sqrt(2*log2 e)
__device__ float g_den[NROWS];                  // denominator sums (atomic accum)
__device__ float g_pos[NROWS];                  // positive logit (natural log domain)
__device__ float g_rpart[32];
__device__ int g_sem;                           // zero-init; reset each launch

static __device__ __forceinline__ float ex2f(float x) {
    float y;
    asm("ex2.approx.f32 %0, %1;" : "=f"(y) : "f"(x));
    return y;
}

static __device__ __forceinline__ void ldsm4(uint32_t& r0, uint32_t& r1,
                                             uint32_t& r2, uint32_t& r3, uint32_t addr) {
    asm volatile("ldmatrix.sync.aligned.m8n8.x4.shared.b16 {%0,%1,%2,%3}, [%4];"
                 : "=r"(r0), "=r"(r1), "=r"(r2), "=r"(r3) : "r"(addr));
}

static __device__ __forceinline__ void mma16816(float c[4], const uint32_t a[4],
                                                const uint32_t b[2]) {
    asm volatile(
        "mma.sync.aligned.m16n8k16.row.col.f32.bf16.bf16.f32 "
        "{%0,%1,%2,%3}, {%4,%5,%6,%7}, {%8,%9}, {%0,%1,%2,%3};"
        : "+f"(c[0]), "+f"(c[1]), "+f"(c[2]), "+f"(c[3])
        : "r"(a[0]), "r"(a[1]), "r"(a[2]), "r"(a[3]), "r"(b[0]), "r"(b[1]));
}

static __device__ __forceinline__ void cpasync16(uint32_t dst, const void* src) {
    asm volatile("cp.async.cg.shared.global [%0], [%1], 16;" :: "r"(dst), "l"(src));
}
#define CP_COMMIT() asm volatile("cp.async.commit_group;")
#define CP_WAIT1()  asm volatile("cp.async.wait_group 1;")
#define CP_WAIT0()  asm volatile("cp.async.wait_group 0;")

// Fill one K-chunk (128 rows x 256B) into swizzled smem: rows of 16x16B chunks,
// swizzle keeps bit3, XORs low 3 bits with row&7. src = tile row0 at kc offset.
static __device__ __forceinline__ void fill_chunk(uint32_t dst, const uint4* src, int tid) {
#pragma unroll
    for (int it = 0; it < 8; it++) {
        int idx = it * 256 + tid;
        int r = idx >> 4, c = idx & 15;
        cpasync16(dst + (uint32_t)(r * 256 + (((c & 8) | ((c & 7) ^ (r & 7))) << 4)),
                  src + r * 32 + c);
    }
}

// ---------------------------------------------------------------------------
// Kernel 1: L2-normalize rows; bf16 scaled by sqrt(2*log2 e). Zeroes g_den.
// ---------------------------------------------------------------------------
__global__ void k_norm(const float* __restrict__ ei, const float* __restrict__ ej) {
    const float SQ = 1.69864362f;  // sqrt(2 * log2(e))
    int warp = threadIdx.x >> 5;
    int lane = threadIdx.x & 31;
    int row = blockIdx.x * 16 + warp * 2;

    const float* s0 = (row < HALF_N) ? (ei + (size_t)row * DDIM)
                                     : (ej + (size_t)(row - HALF_N) * DDIM);
    const float* s1 = s0 + DDIM;
    float4 a0 = ((const float4*)s0)[lane * 2];
    float4 a1 = ((const float4*)s0)[lane * 2 + 1];
    float4 b0 = ((const float4*)s1)[lane * 2];
    float4 b1 = ((const float4*)s1)[lane * 2 + 1];

    float sa = a0.x * a0.x + a0.y * a0.y + a0.z * a0.z + a0.w * a0.w
             + a1.x * a1.x + a1.y * a1.y + a1.z * a1.z + a1.w * a1.w;
    float sb = b0.x * b0.x + b0.y * b0.y + b0.z * b0.z + b0.w * b0.w
             + b1.x * b1.x + b1.y * b1.y + b1.z * b1.z + b1.w * b1.w;
#pragma unroll
    for (int o = 16; o > 0; o >>= 1) {
        sa += __shfl_xor_sync(0xFFFFFFFFu, sa, o);
        sb += __shfl_xor_sync(0xFFFFFFFFu, sb, o);
    }
    float fa = SQ / fmaxf(sqrtf(sa), 1e-12f);
    float fb = SQ / fmaxf(sqrtf(sb), 1e-12f);

    __nv_bfloat162* pa = (__nv_bfloat162*)(g_reps + (size_t)row * DDIM) + lane * 4;
    __nv_bfloat162* pb = (__nv_bfloat162*)(g_reps + (size_t)(row + 1) * DDIM) + lane * 4;
    pa[0] = __floats2bfloat162_rn(a0.x * fa, a0.y * fa);
    pa[1] = __floats2bfloat162_rn(a0.z * fa, a0.w * fa);
    pa[2] = __floats2bfloat162_rn(a1.x * fa, a1.y * fa);
    pa[3] = __floats2bfloat162_rn(a1.z * fa, a1.w * fa);
    pb[0] = __floats2bfloat162_rn(b0.x * fb, b0.y * fb);
    pb[1] = __floats2bfloat162_rn(b0.z * fb, b0.w * fb);
    pb[2] = __floats2bfloat162_rn(b1.x * fb, b1.y * fb);
    pb[3] = __floats2bfloat162_rn(b1.z * fb, b1.w * fb);
    if (lane == 0) { g_den[row] = 0.f; g_den[row + 1] = 0.f; }
}

// ---------------------------------------------------------------------------
// Kernel 2: symmetric fused GEMM + exp + row/col sums, processed as TILE PAIRS
// (128 rows x 256 cols): 8 warps of 64x64; warps 0-3 own tile (rb,c0),
// warps 4-7 own (rb,c1). Halves LDSM bytes per output vs 32x64 tiles.
// K streamed in two 128-element chunks; chunk-sets (A+B0+B1 = 96KB) double-
// buffered via cp.async. 1056 pair-units over the triangle, 7-8 per CTA.
// Odd stripes end in a dup pair: tsel=1 warps compute but skip accumulation.
// ---------------------------------------------------------------------------
__global__ void __launch_bounds__(256, 1) k_main() {
    extern __shared__ unsigned char smem[];
    const float LN2 = 0.6931471805599453f;

    int tid = threadIdx.x;
    int lane = tid & 31;
    int warp = tid >> 5;
    int tsel = warp >> 2;        // which tile of the pair
    int wm = (warp >> 1) & 1;    // 64-row half
    int wn = warp & 1;           // 64-col half within the tile

    uint32_t sb = (uint32_t)__cvta_generic_to_shared(smem);
    const uint4* reps4 = (const uint4*)g_reps;

    // ---- balanced pair-unit schedule: 1056 = 148*7 + 20
    int bId = blockIdx.x;
    int cnt = 7 + (bId < 20 ? 1 : 0);
    int i0 = bId * 7 + (bId < 20 ? bId : 20);

    // decode unit i0 -> (rb, u); stripe rb has ceil((64-rb)/2) units
    int rb = 0, rem = i0;
    while (rem >= ((65 - rb) >> 1)) { rem -= (65 - rb) >> 1; rb++; }
    int u = rem;
    int c0 = rb + 2 * u;
    int c1 = (c0 + 1 <= 63) ? c0 + 1 : c0;   // dup when stripe ends odd

    // next unit
    int rbn = rb, un = u + 1;
    if (un >= ((65 - rbn) >> 1)) { rbn++; un = 0; }

    // Prologue: chunk-set kc=0 -> buf0, kc=1 -> buf1.
    fill_chunk(sb,           reps4 + rb * 4096, tid);
    fill_chunk(sb + 32768u,  reps4 + c0 * 4096, tid);
    fill_chunk(sb + 65536u,  reps4 + c1 * 4096, tid);
    CP_COMMIT();
    fill_chunk(sb + 98304u,           reps4 + rb * 4096 + 16, tid);
    fill_chunk(sb + 98304u + 32768u,  reps4 + c0 * 4096 + 16, tid);
    fill_chunk(sb + 98304u + 65536u,  reps4 + c1 * 4096 + 16, tid);
    CP_COMMIT();
    CP_WAIT1();
    __syncthreads();

    int aRow0 = wm * 64 + (lane & 15);
    int aCo = lane >> 4;
    int bRowBase = wn * 64 + (lane & 7) + ((lane & 16) >> 1);
    int bCo = (lane >> 3) & 1;
    uint32_t Boff = 32768u + (uint32_t)tsel * 32768u;

    float s[8];
#pragma unroll
    for (int i = 0; i < 8; i++) s[i] = 0.f;

#pragma unroll 1
    for (int ui = 0; ; ui++) {
        float acc[4][8][4];
#pragma unroll
        for (int mt = 0; mt < 4; mt++)
#pragma unroll
            for (int nt = 0; nt < 8; nt++)
#pragma unroll
                for (int e = 0; e < 4; e++) acc[mt][nt][e] = 0.f;

        int c0n = rbn + 2 * un;
        int c1n = (c0n + 1 <= 63) ? c0n + 1 : c0n;

#pragma unroll 1
        for (int kc = 0; kc < 2; kc++) {
            uint32_t setb = sb + (uint32_t)kc * 98304u;
            uint32_t Ab = setb, Bb = setb + Boff;

#pragma unroll
            for (int ks = 0; ks < 8; ks++) {
                uint32_t a[4][4];
#pragma unroll
                for (int mt = 0; mt < 4; mt++) {
                    int r = aRow0 + mt * 16;
                    int c = ks * 2 + aCo;
                    uint32_t addr = Ab + r * 256 + (((c & 8) | ((c & 7) ^ (r & 7))) << 4);
                    ldsm4(a[mt][0], a[mt][1], a[mt][2], a[mt][3], addr);
                }
                uint32_t bf[8][2];
#pragma unroll
                for (int nb = 0; nb < 4; nb++) {
                    int r = bRowBase + nb * 16;
                    int c = ks * 2 + bCo;
                    uint32_t addr = Bb + r * 256 + (((c & 8) | ((c & 7) ^ (r & 7))) << 4);
                    uint32_t r0, r1, r2, r3;
                    ldsm4(r0, r1, r2, r3, addr);
                    bf[nb * 2][0] = r0;     bf[nb * 2][1] = r1;
                    bf[nb * 2 + 1][0] = r2; bf[nb * 2 + 1][1] = r3;
                }
#pragma unroll
                for (int mt = 0; mt < 4; mt++)
#pragma unroll
                    for (int nt = 0; nt < 8; nt++)
                        mma16816(acc[mt][nt], a[mt], bf[nt]);
            }

            __syncthreads();   // this chunk-set fully consumed by all warps
            if (ui + 1 < cnt) {
                fill_chunk(setb,           reps4 + rbn * 4096 + kc * 16, tid);
                fill_chunk(setb + 32768u,  reps4 + c0n * 4096 + kc * 16, tid);
                fill_chunk(setb + 65536u,  reps4 + c1n * 4096 + kc * 16, tid);
            }
            CP_COMMIT();       // possibly empty; keeps accounting uniform
            if (ui + 1 < cnt || kc == 0) { CP_WAIT1(); } else { CP_WAIT0(); }
            __syncthreads();
        }

        // ---- Epilogue (skipped entirely by dup-tile warps).
        bool active1 = (c1 != c0);
        if (tsel == 0 || active1) {
            int cbt = tsel ? c1 : c0;
            bool diagblk = (rb == cbt);
            bool posblk = (cbt == rb + 32);
            bool special = diagblk || posblk;
            float cs[16];
#pragma unroll
            for (int q = 0; q < 16; q++) cs[q] = 0.f;

#pragma unroll
            for (int mt = 0; mt < 4; mt++) {
                int lrA = wm * 64 + mt * 16 + (lane >> 2);
                int lrB = lrA + 8;
#pragma unroll
                for (int nt = 0; nt < 8; nt++) {
                    float vx = acc[mt][nt][0], vy = acc[mt][nt][1];
                    float vz = acc[mt][nt][2], vw = acc[mt][nt][3];
                    int lc = wn * 64 + nt * 8 + (lane & 3) * 2;
                    float e0 = ex2f(vx), e1 = ex2f(vy), e2 = ex2f(vz), e3 = ex2f(vw);
                    if (special) {
                        if (lc == lrA) {
                            if (diagblk) e0 = 0.f;
                            else { int gr = rb * 128 + lrA; float pv = vx * LN2;
                                   g_pos[gr] = pv; g_pos[gr + 4096] = pv; }
                        }
                        if (lc + 1 == lrA) {
                            if (diagblk) e1 = 0.f;
                            else { int gr = rb * 128 + lrA; float pv = vy * LN2;
                                   g_pos[gr] = pv; g_pos[gr + 4096] = pv; }
                        }
                        if (lc == lrB) {
                            if (diagblk) e2 = 0.f;
                            else { int gr = rb * 128 + lrB; float pv = vz * LN2;
                                   g_pos[gr] = pv; g_pos[gr + 4096] = pv; }
                        }
                        if (lc + 1 == lrB) {
                            if (diagblk) e3 = 0.f;
                            else { int gr = rb * 128 + lrB; float pv = vw * LN2;
                                   g_pos[gr] = pv; g_pos[gr + 4096] = pv; }
                        }
                    }
                    s[mt * 2 + 0] += e0 + e1;
                    s[mt * 2 + 1] += e2 + e3;
                    cs[nt * 2 + 0] += e0 + e2;
                    cs[nt * 2 + 1] += e1 + e3;
                }
            }

            if (!diagblk) {
#pragma unroll
                for (int q = 0; q < 16; q++) {
                    cs[q] += __shfl_xor_sync(0xFFFFFFFFu, cs[q], 4);
                    cs[q] += __shfl_xor_sync(0xFFFFFFFFu, cs[q], 8);
                    cs[q] += __shfl_xor_sync(0xFFFFFFFFu, cs[q], 16);
                }
                if (lane < 4) {
                    int cbase = cbt * 128 + wn * 64 + lane * 2;
#pragma unroll
                    for (int nt = 0; nt < 8; nt++) {
                        atomicAdd(&g_den[cbase + nt * 8 + 0], cs[nt * 2 + 0]);
                        atomicAdd(&g_den[cbase + nt * 8 + 1], cs[nt * 2 + 1]);
                    }
                }
            }
        }

        // Stripe flush (row sums) on stripe change or at the end.
        bool last = (ui + 1 >= cnt);
        if (last || rbn != rb) {
#pragma unroll
            for (int i2 = 0; i2 < 8; i2++) {
                s[i2] += __shfl_xor_sync(0xFFFFFFFFu, s[i2], 1);
                s[i2] += __shfl_xor_sync(0xFFFFFFFFu, s[i2], 2);
            }
            if ((lane & 3) == 0) {
#pragma unroll
                for (int mt = 0; mt < 4; mt++) {
                    int r = rb * 128 + wm * 64 + mt * 16 + (lane >> 2);
                    atomicAdd(&g_den[r], s[mt * 2]);
                    atomicAdd(&g_den[r + 8], s[mt * 2 + 1]);
                }
            }
#pragma unroll
            for (int i2 = 0; i2 < 8; i2++) s[i2] = 0.f;
        }
        if (last) break;
        rb = rbn; u = un; c0 = c0n; c1 = c1n;
        un = u + 1; rbn = rb;
        if (un >= ((65 - rbn) >> 1)) { rbn++; un = 0; }
    }
}

// ---------------------------------------------------------------------------
// Kernel 3: final reduction -> scalar loss (deterministic fixed-order finish).
// ---------------------------------------------------------------------------
__global__ void k_reduce(float* __restrict__ out) {
    __shared__ float red[256];
    __shared__ int isLast;
    int tid = threadIdx.x;
    int r = blockIdx.x * 256 + tid;
    red[tid] = logf(g_den[r]) - g_pos[r];
    __syncthreads();
#pragma unroll
    for (int o = 128; o > 0; o >>= 1) {
        if (tid < o) red[tid] += red[tid + o];
        __syncthreads();
    }
    if (tid == 0) {
        g_rpart[blockIdx.x] = red[0];
        __threadfence();
        int old = atomicAdd(&g_sem, 1);
        isLast = (old == 31);
    }
    __syncthreads();
    if (tid == 0 && isLast) {
        __threadfence();
        volatile float* rp = g_rpart;
        float a = 0.f;
        for (int i = 0; i < 32; i++) a += rp[i];
        out[0] = a * (1.0f / 8192.0f);
        g_sem = 0;
    }
}

extern "C" void kernel_launch(void* const* d_in, const int* in_sizes, int n_in,
                              void* d_out, int out_size) {
    const float* ei = (const float*)d_in[0];
    const float* ej = (const float*)d_in[1];
    (void)in_sizes; (void)n_in; (void)out_size;

    cudaFuncSetAttribute(k_main, cudaFuncAttributeMaxDynamicSharedMemorySize, 196608);

    k_norm<<<512, 256>>>(ei, ej);
    k_main<<<NCTA, 256, 196608>>>();
    k_reduce<<<32, 256>>>((float*)d_out);
}

// round 14
// speedup vs baseline: 1.1119x; 1.1119x over previous
#include <cuda_runtime.h>
#include <cuda_bf16.h>
#include <stdint.h>
#include <math.h>

#define NROWS 8192
#define HALF_N 4096
#define DDIM 256
#define NCTA 296

// Scratch (allocation-free rule: __device__ globals)
__device__ __nv_bfloat16 g_reps[NROWS * DDIM];  // normalized * sqrt(2*log2 e)
__device__ float g_den[NROWS];                  // denominator sums (atomic accum)
__device__ float g_pos[NROWS];                  // positive logit (natural log domain)
__device__ float g_rpart[32];
__device__ int g_sem;                           // zero-init; reset each launch

static __device__ __forceinline__ float ex2f(float x) {
    float y;
    asm("ex2.approx.f32 %0, %1;" : "=f"(y) : "f"(x));
    return y;
}

static __device__ __forceinline__ void ldsm4(uint32_t& r0, uint32_t& r1,
                                             uint32_t& r2, uint32_t& r3, uint32_t addr) {
    asm volatile("ldmatrix.sync.aligned.m8n8.x4.shared.b16 {%0,%1,%2,%3}, [%4];"
                 : "=r"(r0), "=r"(r1), "=r"(r2), "=r"(r3) : "r"(addr));
}

static __device__ __forceinline__ void mma16816(float c[4], const uint32_t a[4],
                                                const uint32_t b[2]) {
    asm volatile(
        "mma.sync.aligned.m16n8k16.row.col.f32.bf16.bf16.f32 "
        "{%0,%1,%2,%3}, {%4,%5,%6,%7}, {%8,%9}, {%0,%1,%2,%3};"
        : "+f"(c[0]), "+f"(c[1]), "+f"(c[2]), "+f"(c[3])
        : "r"(a[0]), "r"(a[1]), "r"(a[2]), "r"(a[3]), "r"(b[0]), "r"(b[1]));
}

static __device__ __forceinline__ void cpasync16(uint32_t dst, const void* src) {
    asm volatile("cp.async.cg.shared.global [%0], [%1], 16;" :: "r"(dst), "l"(src));
}
#define CP_COMMIT() asm volatile("cp.async.commit_group;")
#define CP_WAIT1()  asm volatile("cp.async.wait_group 1;")
#define CP_WAIT0()  asm volatile("cp.async.wait_group 0;")

// Advance (rb, cb) one tile along the upper triangle (rb-major, cb contiguous).
#define ADV(r_, c_) do { if ((c_) >= 63) { if ((r_) < 63) { (r_)++; (c_) = (r_); } } \
                         else (c_)++; } while (0)

// smem per CTA: A 64KB @0 ; B chunk bufs 16KB @65536, @81920. Total 96KB.
#define SM_B0 65536u
#define SM_B1 81920u
#define SM_TOTAL 98304u

// Fill full A tile (128 rows x 512B, swizzled) with 128 threads.
static __device__ __forceinline__ void fillA(uint32_t dst, const uint4* src, int tid) {
#pragma unroll
    for (int it = 0; it < 32; it++) {
        int idx = it * 128 + tid;
        int r = idx >> 5, c = idx & 31;
        cpasync16(dst + (uint32_t)(r * 32 + (c ^ (r & 7))) * 16, src + idx);
    }
}

// Fill one B chunk: 128 rows x 128B (64 k-elems), swizzled, 128 threads.
// src points at tile base (row0 of col-block); kc selects 16B-unit offset.
static __device__ __forceinline__ void fillB(uint32_t dst, const uint4* src, int kc, int tid) {
#pragma unroll
    for (int it = 0; it < 8; it++) {
        int idx = it * 128 + tid;
        int r = idx >> 3, u = idx & 7;
        cpasync16(dst + (uint32_t)(r * 128 + ((u ^ (r & 7)) << 4)),
                  src + r * 32 + kc * 8 + u);
    }
}

// ---------------------------------------------------------------------------
// Kernel 1: L2-normalize rows; bf16 scaled by sqrt(2*log2 e). Zeroes g_den.
// ---------------------------------------------------------------------------
__global__ void k_norm(const float* __restrict__ ei, const float* __restrict__ ej) {
    const float SQ = 1.69864362f;  // sqrt(2 * log2(e))
    int warp = threadIdx.x >> 5;
    int lane = threadIdx.x & 31;
    int row = blockIdx.x * 16 + warp * 2;

    const float* s0 = (row < HALF_N) ? (ei + (size_t)row * DDIM)
                                     : (ej + (size_t)(row - HALF_N) * DDIM);
    const float* s1 = s0 + DDIM;
    float4 a0 = ((const float4*)s0)[lane * 2];
    float4 a1 = ((const float4*)s0)[lane * 2 + 1];
    float4 b0 = ((const float4*)s1)[lane * 2];
    float4 b1 = ((const float4*)s1)[lane * 2 + 1];

    float sa = a0.x * a0.x + a0.y * a0.y + a0.z * a0.z + a0.w * a0.w
             + a1.x * a1.x + a1.y * a1.y + a1.z * a1.z + a1.w * a1.w;
    float sb = b0.x * b0.x + b0.y * b0.y + b0.z * b0.z + b0.w * b0.w
             + b1.x * b1.x + b1.y * b1.y + b1.z * b1.z + b1.w * b1.w;
#pragma unroll
    for (int o = 16; o > 0; o >>= 1) {
        sa += __shfl_xor_sync(0xFFFFFFFFu, sa, o);
        sb += __shfl_xor_sync(0xFFFFFFFFu, sb, o);
    }
    float fa = SQ / fmaxf(sqrtf(sa), 1e-12f);
    float fb = SQ / fmaxf(sqrtf(sb), 1e-12f);

    __nv_bfloat162* pa = (__nv_bfloat162*)(g_reps + (size_t)row * DDIM) + lane * 4;
    __nv_bfloat162* pb = (__nv_bfloat162*)(g_reps + (size_t)(row + 1) * DDIM) + lane * 4;
    pa[0] = __floats2bfloat162_rn(a0.x * fa, a0.y * fa);
    pa[1] = __floats2bfloat162_rn(a0.z * fa, a0.w * fa);
    pa[2] = __floats2bfloat162_rn(a1.x * fa, a1.y * fa);
    pa[3] = __floats2bfloat162_rn(a1.z * fa, a1.w * fa);
    pb[0] = __floats2bfloat162_rn(b0.x * fb, b0.y * fb);
    pb[1] = __floats2bfloat162_rn(b0.z * fb, b0.w * fb);
    pb[2] = __floats2bfloat162_rn(b1.x * fb, b1.y * fb);
    pb[3] = __floats2bfloat162_rn(b1.z * fb, b1.w * fb);
    if (lane == 0) { g_den[row] = 0.f; g_den[row + 1] = 0.f; }
}

// ---------------------------------------------------------------------------
// Kernel 2: symmetric fused GEMM + exp + row/col sums over the upper triangle.
// 296 CTAs x 128 threads, 2 CTAs/SM (bid and bid+148 share an SM via the
// classic placement LUT; counts chosen so every SM totals 14-15 tiles).
// 4 warps of 64x64 -> per-tile LDSM traffic 256KB (vs 384KB at 32x64).
// A (full K) resident per stripe; B streamed in 64-k chunks, double-buffered.
// ---------------------------------------------------------------------------
__global__ void __launch_bounds__(128, 2) k_main() {
    extern __shared__ unsigned char smem[];
    const float LN2 = 0.6931471805599453f;

    int tid = threadIdx.x;
    int lane = tid & 31;
    int warp = tid >> 5;
    int wm = warp >> 1;   // 0..1: 64-row half
    int wn = warp & 1;    // 0..1: 64-col half

    uint32_t sb = (uint32_t)__cvta_generic_to_shared(smem);
    const uint4* reps4 = (const uint4*)g_reps;

    // ---- schedule: 2080 = 296*7 + 8 ; extras on bids 0..7 (distinct SMs)
    int bId = blockIdx.x;
    int cnt = 7 + (bId < 8 ? 1 : 0);
    int i0 = bId * 7 + (bId < 8 ? bId : 8);

    int rb = 0, rem = i0;
    while (rem >= 64 - rb) { rem -= 64 - rb; rb++; }
    int cb = rb + rem;
    int rbn = rb, cbn = cb; ADV(rbn, cbn);

    // Prologue: A(rb) + B chunks 0,1 of tile 0.
    fillA(sb, reps4 + (size_t)(rb * 128) * 32, tid);
    fillB(sb + SM_B0, reps4 + (size_t)(cb * 128) * 32, 0, tid);
    CP_COMMIT();
    fillB(sb + SM_B1, reps4 + (size_t)(cb * 128) * 32, 1, tid);
    CP_COMMIT();
    CP_WAIT1();
    __syncthreads();

    int aRow0 = wm * 64 + (lane & 15);
    int aCo = lane >> 4;
    int bRowBase = wn * 64 + (lane & 7) + ((lane & 16) >> 1);
    int bCo = (lane >> 3) & 1;

    float acc[4][8][4];
    float s[8];
#pragma unroll
    for (int i = 0; i < 8; i++) s[i] = 0.f;

    int nchunks = cnt * 4;

#pragma unroll 1
    for (int j = 0; j < nchunks; j++) {
        int kc = j & 3;
        uint32_t Bb = sb + ((j & 1) ? SM_B1 : SM_B0);

        if (kc == 0) {
#pragma unroll
            for (int mt = 0; mt < 4; mt++)
#pragma unroll
                for (int nt = 0; nt < 8; nt++)
#pragma unroll
                    for (int e = 0; e < 4; e++) acc[mt][nt][e] = 0.f;
        }

        // ---- compute this 64-k chunk: ks = kc*4 + kk
#pragma unroll
        for (int kk = 0; kk < 4; kk++) {
            int ks = kc * 4 + kk;
            uint32_t a[4][4];
#pragma unroll
            for (int mt = 0; mt < 4; mt++) {
                int r = aRow0 + mt * 16;
                uint32_t addr = sb + r * 512 + ((((ks * 2) + aCo) ^ (r & 7)) << 4);
                ldsm4(a[mt][0], a[mt][1], a[mt][2], a[mt][3], addr);
            }
            uint32_t bf[8][2];
#pragma unroll
            for (int nb = 0; nb < 4; nb++) {
                int r = bRowBase + nb * 16;
                uint32_t addr = Bb + r * 128 + (((kk * 2 + bCo) ^ (r & 7)) << 4);
                uint32_t r0, r1, r2, r3;
                ldsm4(r0, r1, r2, r3, addr);
                bf[nb * 2][0] = r0;     bf[nb * 2][1] = r1;
                bf[nb * 2 + 1][0] = r2; bf[nb * 2 + 1][1] = r3;
            }
#pragma unroll
            for (int mt = 0; mt < 4; mt++)
#pragma unroll
                for (int nt = 0; nt < 8; nt++)
                    mma16816(acc[mt][nt], a[mt], bf[nt]);
        }

        // ---- tile complete at kc==3: epilogue + (maybe) row flush.
        if (kc == 3) {
            bool diagblk = (rb == cb);
            bool posblk = (cb == rb + 32);
            bool special = diagblk || posblk;
            float cs[16];
#pragma unroll
            for (int q = 0; q < 16; q++) cs[q] = 0.f;

#pragma unroll
            for (int mt = 0; mt < 4; mt++) {
                int lrA = wm * 64 + mt * 16 + (lane >> 2);
                int lrB = lrA + 8;
#pragma unroll
                for (int nt = 0; nt < 8; nt++) {
                    float vx = acc[mt][nt][0], vy = acc[mt][nt][1];
                    float vz = acc[mt][nt][2], vw = acc[mt][nt][3];
                    int lc = wn * 64 + nt * 8 + (lane & 3) * 2;
                    float e0 = ex2f(vx), e1 = ex2f(vy), e2 = ex2f(vz), e3 = ex2f(vw);
                    if (special) {
                        if (lc == lrA) {
                            if (diagblk) e0 = 0.f;
                            else { int gr = rb * 128 + lrA; float pv = vx * LN2;
                                   g_pos[gr] = pv; g_pos[gr + 4096] = pv; }
                        }
                        if (lc + 1 == lrA) {
                            if (diagblk) e1 = 0.f;
                            else { int gr = rb * 128 + lrA; float pv = vy * LN2;
                                   g_pos[gr] = pv; g_pos[gr + 4096] = pv; }
                        }
                        if (lc == lrB) {
                            if (diagblk) e2 = 0.f;
                            else { int gr = rb * 128 + lrB; float pv = vz * LN2;
                                   g_pos[gr] = pv; g_pos[gr + 4096] = pv; }
                        }
                        if (lc + 1 == lrB) {
                            if (diagblk) e3 = 0.f;
                            else { int gr = rb * 128 + lrB; float pv = vw * LN2;
                                   g_pos[gr] = pv; g_pos[gr + 4096] = pv; }
                        }
                    }
                    s[mt * 2 + 0] += e0 + e1;
                    s[mt * 2 + 1] += e2 + e3;
                    cs[nt * 2 + 0] += e0 + e2;
                    cs[nt * 2 + 1] += e1 + e3;
                }
            }

            if (!diagblk) {
#pragma unroll
                for (int q = 0; q < 16; q++) {
                    cs[q] += __shfl_xor_sync(0xFFFFFFFFu, cs[q], 4);
                    cs[q] += __shfl_xor_sync(0xFFFFFFFFu, cs[q], 8);
                    cs[q] += __shfl_xor_sync(0xFFFFFFFFu, cs[q], 16);
                }
                if (lane < 4) {
                    int cbase = cb * 128 + wn * 64 + lane * 2;
#pragma unroll
                    for (int nt = 0; nt < 8; nt++) {
                        atomicAdd(&g_den[cbase + nt * 8 + 0], cs[nt * 2 + 0]);
                        atomicAdd(&g_den[cbase + nt * 8 + 1], cs[nt * 2 + 1]);
                    }
                }
            }

            // Row flush when stripe ends (next tile different rb) or all done.
            bool last = (j + 1 >= nchunks);
            if (last || rbn != rb) {
#pragma unroll
                for (int i2 = 0; i2 < 8; i2++) {
                    s[i2] += __shfl_xor_sync(0xFFFFFFFFu, s[i2], 1);
                    s[i2] += __shfl_xor_sync(0xFFFFFFFFu, s[i2], 2);
                }
                if ((lane & 3) == 0) {
#pragma unroll
                    for (int mt = 0; mt < 4; mt++) {
                        int r = rb * 128 + wm * 64 + mt * 16 + (lane >> 2);
                        atomicAdd(&g_den[r], s[mt * 2]);
                        atomicAdd(&g_den[r + 8], s[mt * 2 + 1]);
                    }
                }
#pragma unroll
                for (int i2 = 0; i2 < 8; i2++) s[i2] = 0.f;
            }
        }

        __syncthreads();   // buffer (j&1) fully consumed; A free if reloading

        // ---- prefetch chunk j+2 into the just-freed buffer.
        int jn = j + 2;
        if (jn < nchunks) {
            int cbf = (kc >= 2) ? cbn : cb;   // chunk j+2's tile
            fillB(sb + ((j & 1) ? SM_B1 : SM_B0),
                  reps4 + (size_t)(cbf * 128) * 32, jn & 3, tid);
        }
        CP_COMMIT();       // possibly empty; keeps WAIT1 accounting uniform

        if (kc == 3 && j + 1 < nchunks) {
            // advance to next tile
            int oldrb = rb;
            rb = rbn; cb = cbn;
            ADV(rbn, cbn);
            if (rb != oldrb) {
                fillA(sb, reps4 + (size_t)(rb * 128) * 32, tid);
                CP_COMMIT();
                CP_WAIT0();
            } else {
                CP_WAIT1();
            }
        } else {
            CP_WAIT1();
        }
        __syncthreads();
    }
}

// ---------------------------------------------------------------------------
// Kernel 3: final reduction -> scalar loss (deterministic fixed-order finish).
// ---------------------------------------------------------------------------
__global__ void k_reduce(float* __restrict__ out) {
    __shared__ float red[256];
    __shared__ int isLast;
    int tid = threadIdx.x;
    int r = blockIdx.x * 256 + tid;
    red[tid] = logf(g_den[r]) - g_pos[r];
    __syncthreads();
#pragma unroll
    for (int o = 128; o > 0; o >>= 1) {
        if (tid < o) red[tid] += red[tid + o];
        __syncthreads();
    }
    if (tid == 0) {
        g_rpart[blockIdx.x] = red[0];
        __threadfence();
        int old = atomicAdd(&g_sem, 1);
        isLast = (old == 31);
    }
    __syncthreads();
    if (tid == 0 && isLast) {
        __threadfence();
        volatile float* rp = g_rpart;
        float a = 0.f;
        for (int i = 0; i < 32; i++) a += rp[i];
        out[0] = a * (1.0f / 8192.0f);
        g_sem = 0;
    }
}

extern "C" void kernel_launch(void* const* d_in, const int* in_sizes, int n_in,
                              void* d_out, int out_size) {
    const float* ei = (const float*)d_in[0];
    const float* ej = (const float*)d_in[1];
    (void)in_sizes; (void)n_in; (void)out_size;

    cudaFuncSetAttribute(k_main, cudaFuncAttributeMaxDynamicSharedMemorySize, SM_TOTAL);

    k_norm<<<512, 256>>>(ei, ej);
    k_main<<<NCTA, 128, SM_TOTAL>>>();
    k_reduce<<<32, 256>>>((float*)d_out);
}